// round 3
// baseline (speedup 1.0000x reference)
#include <cuda_runtime.h>
#include <math.h>

// Problem constants
#define BB 16
#define QQ 3000
#define CC 1203
#define BC (BB * CC)                 // 19248
#define BQC ((size_t)BB * QQ * CC)   // 57,744,000
#define QCHUNKS 10
#define QPER (QQ / QCHUNKS)          // 300

// Scratch (no cudaMalloc allowed)
__device__ unsigned g_key[BC];
__device__ float    g_thresh[BC];
__device__ int      g_cnt;
__device__ int      g_mode;          // 1 = mask is uint8/bool, 0 = mask is int32

// monotone float->unsigned encoding for atomicMax
__device__ __forceinline__ unsigned enc_f(float f) {
    unsigned u = __float_as_uint(f);
    return (u & 0x80000000u) ? ~u : (u | 0x80000000u);
}
__device__ __forceinline__ float dec_f(unsigned k) {
    return __uint_as_float((k & 0x80000000u) ? (k & 0x7fffffffu) : ~k);
}

__global__ void k_init() {
    int i = blockIdx.x * blockDim.x + threadIdx.x;
    if (i < BC) g_key[i] = 0u;       // below any real float's key
    if (i == 0) g_cnt = 0;
}

// dtype sniffer: nonzero-byte density over the first BC bytes of the mask.
// bool/uint8 random 0/1 -> ~0.5 ; int32 0/1 read as bytes -> <= 0.25
__global__ void k_detect(const unsigned char* __restrict__ m) {
    int i = blockIdx.x * blockDim.x + threadIdx.x;
    int v = (i < BC && m[i] != 0) ? 1 : 0;
    for (int o = 16; o > 0; o >>= 1) v += __shfl_down_sync(0xffffffffu, v, o);
    if ((threadIdx.x & 31) == 0 && v) atomicAdd(&g_cnt, v);
}

// Pass 1: per-(b,c) max of logits over a chunk of Q, merged via atomicMax.
__global__ void k_max(const float* __restrict__ logits) {
    int c = blockIdx.x * blockDim.x + threadIdx.x;
    if (c >= CC) return;
    int b  = blockIdx.z;
    int q0 = blockIdx.y * QPER;
    const float* p = logits + ((size_t)b * QQ + q0) * CC + c;
    float m = -INFINITY;
#pragma unroll 4
    for (int q = 0; q < QPER; q++)
        m = fmaxf(m, p[(size_t)q * CC]);
    atomicMax(&g_key[b * CC + c], enc_f(m));
}

// thresh[b,c] = 0.5 * sigmoid(max_logit); also finalize mode flag
__global__ void k_thresh() {
    int i = blockIdx.x * blockDim.x + threadIdx.x;
    if (i < BC) {
        float m = dec_f(g_key[i]);
        g_thresh[i] = 0.5f * (1.0f / (1.0f + expf(-m)));
    }
    if (i == 0) g_mode = (8 * g_cnt > 3 * BC) ? 1 : 0;   // density > 0.375 => uint8
}

// Pass 2: one block per (b,q) row. scores/keep elementwise, any-reduce for boxes.
__global__ void k_main(const float* __restrict__ logits,
                       const float* __restrict__ boxes_in,
                       const void* __restrict__ cls_present,
                       float* __restrict__ scores,
                       float* __restrict__ keep,
                       float* __restrict__ boxes) {
    int bq = blockIdx.x;              // b*Q + q
    int b  = bq / QQ;
    size_t base = (size_t)bq * CC;
    const float* lrow = logits + base;
    const float* thr  = g_thresh + b * CC;
    const unsigned char* cp8  = (const unsigned char*)cls_present + (size_t)b * CC;
    const int*           cp32 = (const int*)cls_present + (size_t)b * CC;
    int mode = g_mode;

    int any = 0;
    for (int c = threadIdx.x; c < CC; c += blockDim.x) {
        float x = lrow[c];
        float p = 1.0f / (1.0f + expf(-x));
        int present = mode ? (int)(cp8[c] != 0) : (int)(cp32[c] != 0);
        bool k = (p >= thr[c]) && present;
        any |= (int)k;
        scores[base + c] = k ? p : 0.0f;
        keep[base + c]   = k ? 1.0f : 0.0f;
    }
    int anyall = __syncthreads_or(any);
    if (threadIdx.x < 4) {
        size_t bi = (size_t)bq * 4 + threadIdx.x;
        boxes[bi] = anyall ? boxes_in[bi] : 0.0f;
    }
}

extern "C" void kernel_launch(void* const* d_in, const int* in_sizes, int n_in,
                              void* d_out, int out_size) {
    const float* logits = (const float*)d_in[0];          // [B,Q,C] f32
    const float* pboxes = (const float*)d_in[1];          // [B,Q,4] f32
    // d_in[2] = target_sizes (unused)
    const void*  cpres  = d_in[3];                        // [B,C] bool-ish

    float* out    = (float*)d_out;
    float* scores = out;                 // [B,Q,C]
    float* keep   = out + BQC;           // [B,Q,C] as 0/1 f32
    float* boxes  = out + 2 * BQC;       // [B,Q,4]

    k_init<<<(BC + 255) / 256, 256>>>();
    k_detect<<<(BC + 255) / 256, 256>>>((const unsigned char*)cpres);
    k_max<<<dim3((CC + 255) / 256, QCHUNKS, BB), 256>>>(logits);
    k_thresh<<<(BC + 255) / 256, 256>>>();
    k_main<<<BB * QQ, 256>>>(logits, pboxes, cpres, scores, keep, boxes);
}

// round 12
// speedup vs baseline: 1.9448x; 1.9448x over previous
#include <cuda_runtime.h>
#include <math.h>

#define BB 16
#define QQ 3000
#define CC 1203
#define BC (BB * CC)                 // 19248
#define BQC ((size_t)BB * QQ * CC)   // 57,744,000
#define QCHUNKS 25
#define QPER (QQ / QCHUNKS)          // 120

__device__ unsigned g_key[BC];
__device__ float    g_thresh[BC];
__device__ int      g_mode;          // 1 = mask uint8/bool, 0 = mask int32

__device__ __forceinline__ unsigned enc_f(float f) {
    unsigned u = __float_as_uint(f);
    return (u & 0x80000000u) ? ~u : (u | 0x80000000u);
}
__device__ __forceinline__ float dec_f(unsigned k) {
    return __uint_as_float((k & 0x80000000u) ? (k & 0x7fffffffu) : ~k);
}
__device__ __forceinline__ float fsig(float x) {
    return __fdividef(1.0f, 1.0f + __expf(-x));
}

__global__ void k_init() {
    int i = blockIdx.x * blockDim.x + threadIdx.x;
    if (i < BC) g_key[i] = 0u;
}

// Pass 1: per-(b,c) max over a Q chunk; 8 independent accumulators for MLP.
__global__ void k_max(const float* __restrict__ logits) {
    int c = blockIdx.x * blockDim.x + threadIdx.x;
    if (c >= CC) return;
    int b  = blockIdx.z;
    int q0 = blockIdx.y * QPER;
    const float* p = logits + ((size_t)b * QQ + q0) * CC + c;
    float m0 = -INFINITY, m1 = -INFINITY, m2 = -INFINITY, m3 = -INFINITY;
    float m4 = -INFINITY, m5 = -INFINITY, m6 = -INFINITY, m7 = -INFINITY;
#pragma unroll 1
    for (int q = 0; q < QPER; q += 8) {
        m0 = fmaxf(m0, p[(size_t)(q + 0) * CC]);
        m1 = fmaxf(m1, p[(size_t)(q + 1) * CC]);
        m2 = fmaxf(m2, p[(size_t)(q + 2) * CC]);
        m3 = fmaxf(m3, p[(size_t)(q + 3) * CC]);
        m4 = fmaxf(m4, p[(size_t)(q + 4) * CC]);
        m5 = fmaxf(m5, p[(size_t)(q + 5) * CC]);
        m6 = fmaxf(m6, p[(size_t)(q + 6) * CC]);
        m7 = fmaxf(m7, p[(size_t)(q + 7) * CC]);
    }
    float m = fmaxf(fmaxf(fmaxf(m0, m1), fmaxf(m2, m3)),
                    fmaxf(fmaxf(m4, m5), fmaxf(m6, m7)));
    atomicMax(&g_key[b * CC + c], enc_f(m));
}

// thresh[b,c] = 0.5*sigmoid(max); block 0 warp 0 also sniffs mask dtype.
__global__ void k_thresh(const unsigned char* __restrict__ mask) {
    int i = blockIdx.x * blockDim.x + threadIdx.x;
    if (i < BC) g_thresh[i] = 0.5f * fsig(dec_f(g_key[i]));
    if (blockIdx.x == 0 && threadIdx.x < 32) {
        int cnt = 0;
        for (int j = 0; j < 32; j++)
            cnt += (mask[threadIdx.x * 32 + j] != 0) ? 1 : 0;
        for (int o = 16; o > 0; o >>= 1) cnt += __shfl_down_sync(0xffffffffu, cnt, o);
        if (threadIdx.x == 0) g_mode = (cnt > 384) ? 1 : 0;  // 1024-byte sample
    }
}

// Pass 2: one WARP per (b,q) row; float4 main path with alignment prologue/tail.
__global__ void k_main(const float* __restrict__ logits,
                       const float* __restrict__ boxes_in,
                       const void* __restrict__ cls_present,
                       float* __restrict__ scores,
                       float* __restrict__ keep,
                       float* __restrict__ boxes) {
    int warp = (blockIdx.x * blockDim.x + threadIdx.x) >> 5;
    int lane = threadIdx.x & 31;
    if (warp >= BB * QQ) return;
    int bq = warp;
    int b  = bq / QQ;
    size_t base = (size_t)bq * CC;
    const float* lrow = logits + base;
    float* srow = scores + base;
    float* krow = keep + base;
    const float* thr = g_thresh + b * CC;
    const unsigned char* cp8  = (const unsigned char*)cls_present + (size_t)b * CC;
    const int*           cp32 = (const int*)cls_present + (size_t)b * CC;
    const bool m8 = (g_mode != 0);

    bool any = false;
    int s = (int)((4 - (base & 3)) & 3);   // scalars until 16B-aligned

    if (lane < s) {
        int c = lane;
        float p = fsig(lrow[c]);
        bool k = (p >= thr[c]) && (m8 ? (cp8[c] != 0) : (cp32[c] != 0));
        any |= k;
        srow[c] = k ? p : 0.0f;
        krow[c] = k ? 1.0f : 0.0f;
    }

    int nv = (CC - s) >> 2;                // float4 count
    const float4* lv = (const float4*)(lrow + s);
    float4*       sv = (float4*)(srow + s);
    float4*       kv = (float4*)(krow + s);
    for (int i = lane; i < nv; i += 32) {
        float4 x = lv[i];
        int c0 = s + 4 * i;
        float4 sc, kp;
        float p0 = fsig(x.x), p1 = fsig(x.y), p2 = fsig(x.z), p3 = fsig(x.w);
        bool k0 = (p0 >= thr[c0 + 0]) && (m8 ? (cp8[c0 + 0] != 0) : (cp32[c0 + 0] != 0));
        bool k1 = (p1 >= thr[c0 + 1]) && (m8 ? (cp8[c0 + 1] != 0) : (cp32[c0 + 1] != 0));
        bool k2 = (p2 >= thr[c0 + 2]) && (m8 ? (cp8[c0 + 2] != 0) : (cp32[c0 + 2] != 0));
        bool k3 = (p3 >= thr[c0 + 3]) && (m8 ? (cp8[c0 + 3] != 0) : (cp32[c0 + 3] != 0));
        any |= (k0 | k1 | k2 | k3);
        sc.x = k0 ? p0 : 0.0f;  kp.x = k0 ? 1.0f : 0.0f;
        sc.y = k1 ? p1 : 0.0f;  kp.y = k1 ? 1.0f : 0.0f;
        sc.z = k2 ? p2 : 0.0f;  kp.z = k2 ? 1.0f : 0.0f;
        sc.w = k3 ? p3 : 0.0f;  kp.w = k3 ? 1.0f : 0.0f;
        sv[i] = sc;
        kv[i] = kp;
    }

    for (int c = s + 4 * nv + lane; c < CC; c += 32) {
        float p = fsig(lrow[c]);
        bool k = (p >= thr[c]) && (m8 ? (cp8[c] != 0) : (cp32[c] != 0));
        any |= k;
        srow[c] = k ? p : 0.0f;
        krow[c] = k ? 1.0f : 0.0f;
    }

    bool anyall = __ballot_sync(0xffffffffu, any) != 0u;
    if (lane < 4) {
        size_t bi = (size_t)bq * 4 + lane;
        boxes[bi] = anyall ? boxes_in[bi] : 0.0f;
    }
}

extern "C" void kernel_launch(void* const* d_in, const int* in_sizes, int n_in,
                              void* d_out, int out_size) {
    const float* logits = (const float*)d_in[0];
    const float* pboxes = (const float*)d_in[1];
    const void*  cpres  = d_in[3];

    float* out    = (float*)d_out;
    float* scores = out;
    float* keep   = out + BQC;
    float* boxes  = out + 2 * BQC;

    k_init<<<(BC + 255) / 256, 256>>>();
    k_max<<<dim3((CC + 255) / 256, QCHUNKS, BB), 256>>>(logits);
    k_thresh<<<(BC + 255) / 256, 256>>>((const unsigned char*)cpres);
    int warps = BB * QQ;                          // 48000 rows
    k_main<<<(warps * 32 + 255) / 256, 256>>>(logits, pboxes, cpres, scores, keep, boxes);
}

// round 15
// speedup vs baseline: 2.0070x; 1.0320x over previous
#include <cuda_runtime.h>
#include <math.h>

#define BB 16
#define QQ 3000
#define CC 1203
#define BC (BB * CC)                 // 19248
#define BQC ((size_t)BB * QQ * CC)   // 57,744,000
#define QCHUNKS 25
#define QPER (QQ / QCHUNKS)          // 120
#define ROWS_PER_BLK 8               // 8 warps/block, one row each

__device__ unsigned g_key[BC];
__device__ float    g_thresh[BC];
__device__ int      g_mode;          // 1 = mask uint8/bool, 0 = mask int32

__device__ __forceinline__ unsigned enc_f(float f) {
    unsigned u = __float_as_uint(f);
    return (u & 0x80000000u) ? ~u : (u | 0x80000000u);
}
__device__ __forceinline__ float dec_f(unsigned k) {
    return __uint_as_float((k & 0x80000000u) ? (k & 0x7fffffffu) : ~k);
}
__device__ __forceinline__ float fsig(float x) {
    return __fdividef(1.0f, 1.0f + __expf(-x));
}

__global__ void k_init() {
    int i = blockIdx.x * blockDim.x + threadIdx.x;
    if (i < BC) g_key[i] = 0u;
}

// Pass 1: per-(b,c) max over a Q chunk; 8 independent accumulators for MLP.
__global__ void k_max(const float* __restrict__ logits) {
    int c = blockIdx.x * blockDim.x + threadIdx.x;
    if (c >= CC) return;
    int b  = blockIdx.z;
    int q0 = blockIdx.y * QPER;
    const float* p = logits + ((size_t)b * QQ + q0) * CC + c;
    float m0 = -INFINITY, m1 = -INFINITY, m2 = -INFINITY, m3 = -INFINITY;
    float m4 = -INFINITY, m5 = -INFINITY, m6 = -INFINITY, m7 = -INFINITY;
#pragma unroll 1
    for (int q = 0; q < QPER; q += 8) {
        m0 = fmaxf(m0, p[(size_t)(q + 0) * CC]);
        m1 = fmaxf(m1, p[(size_t)(q + 1) * CC]);
        m2 = fmaxf(m2, p[(size_t)(q + 2) * CC]);
        m3 = fmaxf(m3, p[(size_t)(q + 3) * CC]);
        m4 = fmaxf(m4, p[(size_t)(q + 4) * CC]);
        m5 = fmaxf(m5, p[(size_t)(q + 5) * CC]);
        m6 = fmaxf(m6, p[(size_t)(q + 6) * CC]);
        m7 = fmaxf(m7, p[(size_t)(q + 7) * CC]);
    }
    float m = fmaxf(fmaxf(fmaxf(m0, m1), fmaxf(m2, m3)),
                    fmaxf(fmaxf(m4, m5), fmaxf(m6, m7)));
    atomicMax(&g_key[b * CC + c], enc_f(m));
}

// thresh[b,c] = 0.5*sigmoid(max); block 0 warp 0 also sniffs mask dtype.
__global__ void k_thresh(const unsigned char* __restrict__ mask) {
    int i = blockIdx.x * blockDim.x + threadIdx.x;
    if (i < BC) g_thresh[i] = 0.5f * fsig(dec_f(g_key[i]));
    if (blockIdx.x == 0 && threadIdx.x < 32) {
        int cnt = 0;
        for (int j = 0; j < 32; j++)
            cnt += (mask[threadIdx.x * 32 + j] != 0) ? 1 : 0;
        for (int o = 16; o > 0; o >>= 1) cnt += __shfl_down_sync(0xffffffffu, cnt, o);
        if (threadIdx.x == 0) g_mode = (cnt > 384) ? 1 : 0;  // 1024-byte sample
    }
}

// Pass 2: CTA = 8 rows of ONE batch. Mask-fused thresholds staged in smem once;
// inner loop is 1 LDG.128 + 4 LDS + 2 STG.128 per 4 elements.
__global__ void k_main(const float* __restrict__ logits,
                       const float* __restrict__ boxes_in,
                       const void* __restrict__ cls_present,
                       float* __restrict__ scores,
                       float* __restrict__ keep,
                       float* __restrict__ boxes) {
    __shared__ float thr_eff[CC];

    int b = blockIdx.y;
    int tid = threadIdx.x;

    // Prologue: fuse mask into threshold (absent class -> +INF, never kept)
    {
        const float* thr = g_thresh + b * CC;
        const unsigned char* cp8  = (const unsigned char*)cls_present + (size_t)b * CC;
        const int*           cp32 = (const int*)cls_present + (size_t)b * CC;
        const bool m8 = (g_mode != 0);
        for (int c = tid; c < CC; c += 256) {
            bool present = m8 ? (cp8[c] != 0) : (cp32[c] != 0);
            thr_eff[c] = present ? thr[c] : INFINITY;
        }
    }
    __syncthreads();

    int warp = tid >> 5;
    int lane = tid & 31;
    int q  = blockIdx.x * ROWS_PER_BLK + warp;
    int bq = b * QQ + q;
    size_t base = (size_t)bq * CC;
    const float* lrow = logits + base;
    float* srow = scores + base;
    float* krow = keep + base;

    bool any = false;
    int s = (int)((4 - (base & 3)) & 3);   // scalars until 16B-aligned

    if (lane < s) {
        int c = lane;
        float p = fsig(lrow[c]);
        bool k = (p >= thr_eff[c]);
        any |= k;
        srow[c] = k ? p : 0.0f;
        krow[c] = k ? 1.0f : 0.0f;
    }

    int nv = (CC - s) >> 2;                // float4 count
    const float4* lv = (const float4*)(lrow + s);
    float4*       sv = (float4*)(srow + s);
    float4*       kv = (float4*)(krow + s);
    for (int i = lane; i < nv; i += 32) {
        float4 x = lv[i];
        int c0 = s + 4 * i;
        float4 sc, kp;
        float p0 = fsig(x.x), p1 = fsig(x.y), p2 = fsig(x.z), p3 = fsig(x.w);
        bool k0 = (p0 >= thr_eff[c0 + 0]);
        bool k1 = (p1 >= thr_eff[c0 + 1]);
        bool k2 = (p2 >= thr_eff[c0 + 2]);
        bool k3 = (p3 >= thr_eff[c0 + 3]);
        any |= (k0 | k1 | k2 | k3);
        sc.x = k0 ? p0 : 0.0f;  kp.x = k0 ? 1.0f : 0.0f;
        sc.y = k1 ? p1 : 0.0f;  kp.y = k1 ? 1.0f : 0.0f;
        sc.z = k2 ? p2 : 0.0f;  kp.z = k2 ? 1.0f : 0.0f;
        sc.w = k3 ? p3 : 0.0f;  kp.w = k3 ? 1.0f : 0.0f;
        sv[i] = sc;
        kv[i] = kp;
    }

    for (int c = s + 4 * nv + lane; c < CC; c += 32) {
        float p = fsig(lrow[c]);
        bool k = (p >= thr_eff[c]);
        any |= k;
        srow[c] = k ? p : 0.0f;
        krow[c] = k ? 1.0f : 0.0f;
    }

    bool anyall = __ballot_sync(0xffffffffu, any) != 0u;
    if (lane < 4) {
        size_t bi = (size_t)bq * 4 + lane;
        boxes[bi] = anyall ? boxes_in[bi] : 0.0f;
    }
}

extern "C" void kernel_launch(void* const* d_in, const int* in_sizes, int n_in,
                              void* d_out, int out_size) {
    const float* logits = (const float*)d_in[0];
    const float* pboxes = (const float*)d_in[1];
    const void*  cpres  = d_in[3];

    float* out    = (float*)d_out;
    float* scores = out;
    float* keep   = out + BQC;
    float* boxes  = out + 2 * BQC;

    k_init<<<(BC + 255) / 256, 256>>>();
    k_max<<<dim3((CC + 255) / 256, QCHUNKS, BB), 256>>>(logits);
    k_thresh<<<(BC + 255) / 256, 256>>>((const unsigned char*)cpres);
    k_main<<<dim3(QQ / ROWS_PER_BLK, BB), 256>>>(logits, pboxes, cpres, scores, keep, boxes);
}